// round 15
// baseline (speedup 1.0000x reference)
#include <cuda_runtime.h>
#include <cuda_bf16.h>
#include <cstdint>

#define NN   100000
#define FIN  1024
#define HH   8
#define DD   16
#define CC   128
#define EE   600000
#define PP   3
#define OUTC 3
#define NEG  0.2f

#define KSA  40    // A smem k-stride (bf16 elems), padded
#define NSB  136   // B smem n-stride (bf16 elems), padded

// dynamic smem layout (bytes)
#define OFF_RAWA  0                       // 2 x 128*32 f32      = 32768
#define OFF_ASH   32768                   // 2 x 128*KSA u16     = 20480
#define OFF_ASL   (32768 + 20480)         // 2 x 128*KSA u16     = 20480
#define OFF_BSH   (32768 + 40960)         // 2 x 32*NSB u16      = 17408
#define OFF_BSL   (32768 + 40960 + 17408) // 2 x 32*NSB u16      = 17408
#define SMEMSZ    (32768 + 40960 + 34816)

#define NTHREADS  384                     // 8 MMA warps + 4 producer warps

// named barriers: READY[b] = 1+b (producers arrive, consumers sync)
//                 FREE[b]  = 3+b (consumers arrive, producers sync)
#define BAR_SYNC_N(id)   asm volatile("bar.sync %0, 384;"   :: "r"(id))
#define BAR_ARRIVE_N(id) asm volatile("bar.arrive %0, 384;" :: "r"(id))

// ---------------- scratch (static device globals; no allocs) ----------------
__device__ float g_h[(size_t)NN * CC];
__device__ float g_outs[(size_t)PP * NN * CC];
__device__ float g_p[(size_t)PP * EE * HH];
__device__ float g_als[(size_t)PP * NN * HH];
__device__ float g_ald[(size_t)PP * NN * HH];
__device__ float g_denom[(size_t)PP * NN * HH];
__device__ float g_w[PP * CC];
__device__ float g_beta[PP];
__device__ int   g_is64;
#define WPROJ_ELEMS (FIN * CC)
#define KW_ELEMS    (CC * CC)
__device__ __nv_bfloat16 g_WH[WPROJ_ELEMS + KW_ELEMS];
__device__ __nv_bfloat16 g_WL[WPROJ_ELEMS + KW_ELEMS];

// ---------------- helpers ----------------
__device__ __forceinline__ void red_add_v4(float* addr, float4 v) {
    asm volatile("red.global.add.v4.f32 [%0], {%1,%2,%3,%4};"
                 :: "l"(addr), "f"(v.x), "f"(v.y), "f"(v.z), "f"(v.w)
                 : "memory");
}

__device__ __forceinline__ long long load_idx(const void* ei, size_t pos) {
    if (g_is64) return ((const long long*)ei)[pos];
    return (long long)((const int*)ei)[pos];
}

// fast hi/lo split: 2 packed cvt + bit-recover hi as f32
__device__ __forceinline__ void split2f(float v0, float v1, uint32_t& hi, uint32_t& lo) {
    asm("cvt.rn.bf16x2.f32 %0, %1, %2;" : "=r"(hi) : "f"(v1), "f"(v0));
    float h0 = __uint_as_float(hi << 16);
    float h1 = __uint_as_float(hi & 0xffff0000u);
    float l0 = v0 - h0;
    float l1 = v1 - h1;
    asm("cvt.rn.bf16x2.f32 %0, %1, %2;" : "=r"(lo) : "f"(l1), "f"(l0));
}

__device__ __forceinline__ void mma16816(float* c, const uint32_t* a, const uint32_t* b) {
    asm volatile(
        "mma.sync.aligned.m16n8k16.row.col.f32.bf16.bf16.f32 "
        "{%0,%1,%2,%3}, {%4,%5,%6,%7}, {%8,%9}, {%0,%1,%2,%3};"
        : "+f"(c[0]), "+f"(c[1]), "+f"(c[2]), "+f"(c[3])
        : "r"(a[0]), "r"(a[1]), "r"(a[2]), "r"(a[3]), "r"(b[0]), "r"(b[1]));
}

__device__ __forceinline__ void ldm_x2_t(uint32_t& r0, uint32_t& r1, uint32_t saddr) {
    asm volatile("ldmatrix.sync.aligned.m8n8.x2.trans.shared.b16 {%0,%1}, [%2];"
                 : "=r"(r0), "=r"(r1) : "r"(saddr));
}

__device__ __forceinline__ void cp16(void* sdst, const void* gsrc) {
    uint32_t s = (uint32_t)__cvta_generic_to_shared(sdst);
    asm volatile("cp.async.cg.shared.global [%0], [%1], 16;" :: "r"(s), "l"(gsrc));
}

// ---------------- dtype probe ----------------
__global__ void probe_kernel(const void* ei) {
    if (threadIdx.x == 0 && blockIdx.x == 0) {
        const long long* p64 = (const long long*)ei;
        int ok = 1;
#pragma unroll
        for (int i = 0; i < 16; i++) {
            long long v = p64[i];
            if (v < 0 || v >= NN) ok = 0;
        }
        g_is64 = ok;
    }
}

// ---------------- preconvert weights to bf16 hi/lo (k-major) ----------------
__global__ void convW_kernel(const float* __restrict__ Wp,
                             const float* __restrict__ kW)
{
    int i = blockIdx.x * blockDim.x + threadIdx.x;
    if (i >= WPROJ_ELEMS + KW_ELEMS) return;
    float v = (i < WPROJ_ELEMS) ? Wp[i] : kW[i - WPROJ_ELEMS];
    __nv_bfloat16 h = __float2bfloat16_rn(v);
    g_WH[i] = h;
    g_WL[i] = __float2bfloat16_rn(v - __bfloat162float(h));
}

// ---------------- zero accumulators ----------------
__global__ void zero_kernel() {
    size_t i = (size_t)blockIdx.x * blockDim.x + threadIdx.x;
    size_t stride = (size_t)gridDim.x * blockDim.x;
    float4 z = make_float4(0.f, 0.f, 0.f, 0.f);
    const size_t n_outs4 = (size_t)PP * NN * CC / 4;
    float4* po = (float4*)g_outs;
    for (size_t j = i; j < n_outs4; j += stride) po[j] = z;
    const size_t n_den4 = (size_t)PP * NN * HH / 4;
    float4* pd = (float4*)g_denom;
    for (size_t j = i; j < n_den4; j += stride) pd[j] = z;
    if (i < PP * CC) g_w[i] = 0.f;
}

// ------------- warp-specialized bf16-split HMMA GEMM -----------------------
// warps 0-7: MMA consumers (accumulators). warps 8-11: producers (cp.async +
// fp32->bf16 hi/lo convert). Named-barrier handshake, double-buffered tiles.
template <int MODE>
__global__ __launch_bounds__(NTHREADS, 1) void gemm_bf16(
    const float* __restrict__ Aext, const float* __restrict__ bias, int M, int K)
{
    extern __shared__ __align__(16) char dsm[];
    float*    rawA = (float*)(dsm + OFF_RAWA);
    uint16_t* ASH  = (uint16_t*)(dsm + OFF_ASH);
    uint16_t* ASL  = (uint16_t*)(dsm + OFF_ASL);
    uint16_t* BSH  = (uint16_t*)(dsm + OFF_BSH);
    uint16_t* BSL  = (uint16_t*)(dsm + OFF_BSL);
    __shared__ float colsum[128];

    const float* __restrict__ A = (MODE == 0) ? Aext : g_outs;
    const __nv_bfloat16* __restrict__ BH = (MODE == 0) ? g_WH : (g_WH + WPROJ_ELEMS);
    const __nv_bfloat16* __restrict__ BL = (MODE == 0) ? g_WL : (g_WL + WPROJ_ELEMS);

    int tid  = threadIdx.x;
    int lane = tid & 31;
    int wid  = tid >> 5;
    int row0 = blockIdx.x * 128;
    int nT = K / 32;

    if (wid >= 8) {
        // ===================== PRODUCER =====================
        int pid = tid - 256;   // 0..127

#define P_ISSUE(tt) do {                                                         \
            int _s = (tt) & 1;                                                   \
            int _k0 = (tt) * 32;                                                 \
            float* _ra = rawA + _s * 4096;                                       \
            _Pragma("unroll")                                                    \
            for (int j = 0; j < 8; j++) {                                        \
                int c = pid + j * 128;                                           \
                int r_ = c >> 3;                                                 \
                int k4_ = (c & 7) * 4;                                           \
                int gr = row0 + r_; if (gr > M - 1) gr = M - 1;                  \
                cp16(&_ra[r_ * 32 + k4_], &A[(size_t)gr * K + _k0 + k4_]);       \
            }                                                                    \
            uint16_t* _bh = BSH + _s * 32 * NSB;                                 \
            uint16_t* _bl = BSL + _s * 32 * NSB;                                 \
            _Pragma("unroll")                                                    \
            for (int j = 0; j < 4; j++) {                                        \
                int c = pid + j * 128;                                           \
                int r_ = c >> 4;                                                 \
                int c8_ = (c & 15) * 8;                                          \
                cp16(&_bh[r_ * NSB + c8_], &BH[(size_t)(_k0 + r_) * 128 + c8_]); \
                cp16(&_bl[r_ * NSB + c8_], &BL[(size_t)(_k0 + r_) * 128 + c8_]); \
            }                                                                    \
            asm volatile("cp.async.commit_group;");                              \
        } while (0)

#define P_CONVERT(tt) do {                                                       \
            int _s = (tt) & 1;                                                   \
            float* _ra = rawA + _s * 4096;                                       \
            uint16_t* _ah = ASH + _s * 128 * KSA;                                \
            uint16_t* _al = ASL + _s * 128 * KSA;                                \
            _Pragma("unroll")                                                    \
            for (int j = 0; j < 8; j++) {                                        \
                int c = pid + j * 128;                                           \
                int r_ = c >> 3;                                                 \
                int k4_ = (c & 7) * 4;                                           \
                float4 v = *(const float4*)&_ra[r_ * 32 + k4_];                  \
                if (MODE == 1) {                                                 \
                    v.x = fmaxf(v.x, 0.f); v.y = fmaxf(v.y, 0.f);                \
                    v.z = fmaxf(v.z, 0.f); v.w = fmaxf(v.w, 0.f);                \
                }                                                                \
                uint32_t h01, l01, h23, l23;                                     \
                split2f(v.x, v.y, h01, l01);                                     \
                split2f(v.z, v.w, h23, l23);                                     \
                *(uint32_t*)&_ah[r_ * KSA + k4_]     = h01;                      \
                *(uint32_t*)&_ah[r_ * KSA + k4_ + 2] = h23;                      \
                *(uint32_t*)&_al[r_ * KSA + k4_]     = l01;                      \
                *(uint32_t*)&_al[r_ * KSA + k4_ + 2] = l23;                      \
            }                                                                    \
        } while (0)

        P_ISSUE(0);
        for (int t = 0; t < nT; t++) {
            int b = t & 1;
            if (t + 1 < nT) {
                if (t + 1 >= 2) BAR_SYNC_N(3 + ((t + 1) & 1));   // FREE[(t+1)&1]
                P_ISSUE(t + 1);
                asm volatile("cp.async.wait_group 1;");
            } else {
                asm volatile("cp.async.wait_group 0;");
            }
            P_CONVERT(t);
            asm volatile("membar.cta;");
            BAR_ARRIVE_N(1 + b);                                 // READY[b]
        }
#undef P_ISSUE
#undef P_CONVERT
    }

    // consumer accumulators (only warps 0-7 use them)
    float acc[2][8][4];
#pragma unroll
    for (int mt = 0; mt < 2; mt++)
#pragma unroll
        for (int nt = 0; nt < 8; nt++)
#pragma unroll
            for (int j = 0; j < 4; j++) acc[mt][nt][j] = 0.f;

    int wm = wid & 3;
    int wn = wid >> 2;
    int g  = lane >> 2;
    int t4 = lane & 3;

    if (wid < 8) {
        // ===================== CONSUMER =====================
        for (int t = 0; t < nT; t++) {
            int b = t & 1;
            BAR_SYNC_N(1 + b);                                   // READY[b]
            const uint16_t* aH = ASH + b * 128 * KSA;
            const uint16_t* aL = ASL + b * 128 * KSA;
            const uint16_t* bH = BSH + b * 32 * NSB;
            const uint16_t* bL = BSL + b * 32 * NSB;
#pragma unroll
            for (int ks = 0; ks < 32; ks += 16) {
                uint32_t ah[2][4], al[2][4];
#pragma unroll
                for (int mt = 0; mt < 2; mt++) {
                    int r = wm * 32 + mt * 16 + g;
                    const uint16_t* pH = &aH[r * KSA + ks + 2 * t4];
                    const uint16_t* pL = &aL[r * KSA + ks + 2 * t4];
                    ah[mt][0] = *(const uint32_t*)pH;
                    ah[mt][1] = *(const uint32_t*)(pH + 8 * KSA);
                    ah[mt][2] = *(const uint32_t*)(pH + 8);
                    ah[mt][3] = *(const uint32_t*)(pH + 8 * KSA + 8);
                    al[mt][0] = *(const uint32_t*)pL;
                    al[mt][1] = *(const uint32_t*)(pL + 8 * KSA);
                    al[mt][2] = *(const uint32_t*)(pL + 8);
                    al[mt][3] = *(const uint32_t*)(pL + 8 * KSA + 8);
                }
#pragma unroll
                for (int nt = 0; nt < 8; nt++) {
                    int nb2 = wn * 64 + nt * 8;
                    uint32_t bh[2], bl[2];
                    uint32_t srcH = (uint32_t)__cvta_generic_to_shared(
                        &bH[(ks + (lane & 15)) * NSB + nb2]);
                    uint32_t srcL = (uint32_t)__cvta_generic_to_shared(
                        &bL[(ks + (lane & 15)) * NSB + nb2]);
                    ldm_x2_t(bh[0], bh[1], srcH);
                    ldm_x2_t(bl[0], bl[1], srcL);
#pragma unroll
                    for (int mt = 0; mt < 2; mt++) {
                        mma16816(acc[mt][nt], ah[mt], bh);
                        mma16816(acc[mt][nt], ah[mt], bl);
                        mma16816(acc[mt][nt], al[mt], bh);
                    }
                }
            }
            BAR_ARRIVE_N(3 + b);                                 // FREE[b]
        }
    }

    // ===================== EPILOGUE =====================
    if (MODE == 0) {
        if (wid < 8) {
#pragma unroll
            for (int mt = 0; mt < 2; mt++) {
                int r0 = row0 + wm * 32 + mt * 16 + g;
#pragma unroll
                for (int nt = 0; nt < 8; nt++) {
                    int c = wn * 64 + nt * 8 + 2 * t4;
                    float b0 = bias[c], b1 = bias[c + 1];
                    if (r0 < M) {
                        float2 s = make_float2(acc[mt][nt][0] + b0, acc[mt][nt][1] + b1);
                        *(float2*)&g_h[(size_t)r0 * 128 + c] = s;
                    }
                    int r1 = r0 + 8;
                    if (r1 < M) {
                        float2 s = make_float2(acc[mt][nt][2] + b0, acc[mt][nt][3] + b1);
                        *(float2*)&g_h[(size_t)r1 * 128 + c] = s;
                    }
                }
            }
        }
    } else {
        bool crossing = (row0 / NN) != ((row0 + 127) / NN);
        if (!crossing) {
            int p = row0 / NN;
            if (tid < 128) colsum[tid] = 0.f;
            __syncthreads();
            if (wid < 8) {
                float cs[8][2];
#pragma unroll
                for (int nt = 0; nt < 8; nt++) { cs[nt][0] = 0.f; cs[nt][1] = 0.f; }
#pragma unroll
                for (int mt = 0; mt < 2; mt++) {
                    int r0 = row0 + wm * 32 + mt * 16 + g;
                    int r1 = r0 + 8;
#pragma unroll
                    for (int nt = 0; nt < 8; nt++) {
                        int c = wn * 64 + nt * 8 + 2 * t4;
                        float b0 = bias[c], b1 = bias[c + 1];
                        if (r0 < M) {
                            cs[nt][0] += tanhf(acc[mt][nt][0] + b0);
                            cs[nt][1] += tanhf(acc[mt][nt][1] + b1);
                        }
                        if (r1 < M) {
                            cs[nt][0] += tanhf(acc[mt][nt][2] + b0);
                            cs[nt][1] += tanhf(acc[mt][nt][3] + b1);
                        }
                    }
                }
#pragma unroll
                for (int nt = 0; nt < 8; nt++) {
#pragma unroll
                    for (int m = 4; m <= 16; m <<= 1) {
                        cs[nt][0] += __shfl_xor_sync(0xffffffffu, cs[nt][0], m);
                        cs[nt][1] += __shfl_xor_sync(0xffffffffu, cs[nt][1], m);
                    }
                }
                if (g == 0) {
#pragma unroll
                    for (int nt = 0; nt < 8; nt++) {
                        int c = wn * 64 + nt * 8 + 2 * t4;
                        atomicAdd(&colsum[c], cs[nt][0]);
                        atomicAdd(&colsum[c + 1], cs[nt][1]);
                    }
                }
            }
            __syncthreads();
            if (tid < 128) atomicAdd(&g_w[p * CC + tid], colsum[tid]);
        } else if (wid < 8) {
#pragma unroll
            for (int mt = 0; mt < 2; mt++) {
                int r0 = row0 + wm * 32 + mt * 16 + g;
                int r1 = r0 + 8;
#pragma unroll
                for (int nt = 0; nt < 8; nt++) {
                    int c = wn * 64 + nt * 8 + 2 * t4;
                    float b0 = bias[c], b1 = bias[c + 1];
                    if (r0 < M) {
                        atomicAdd(&g_w[(r0 / NN) * CC + c],     tanhf(acc[mt][nt][0] + b0));
                        atomicAdd(&g_w[(r0 / NN) * CC + c + 1], tanhf(acc[mt][nt][1] + b1));
                    }
                    if (r1 < M) {
                        atomicAdd(&g_w[(r1 / NN) * CC + c],     tanhf(acc[mt][nt][2] + b0));
                        atomicAdd(&g_w[(r1 / NN) * CC + c + 1], tanhf(acc[mt][nt][3] + b1));
                    }
                }
            }
        }
    }
}

// ------- attention logits, all metapaths, 2 nodes per thread -------
__global__ void alsd_all_kernel(const float* __restrict__ asrc,
                                const float* __restrict__ adst)
{
    int i = blockIdx.x * blockDim.x + threadIdx.x;
    if (i >= (NN / 2) * HH) return;
    int h  = i & 7;
    int n0 = (i >> 3) * 2;
    int n1 = n0 + 1;
    float4 hv0[4], hv1[4];
    const float4* hp0 = (const float4*)&g_h[(size_t)n0 * CC + h * DD];
    const float4* hp1 = (const float4*)&g_h[(size_t)n1 * CC + h * DD];
#pragma unroll
    for (int j = 0; j < 4; j++) { hv0[j] = hp0[j]; hv1[j] = hp1[j]; }
#pragma unroll
    for (int p = 0; p < PP; p++) {
        const float4* as = (const float4*)&asrc[(p * HH + h) * DD];
        const float4* ad = (const float4*)&adst[(p * HH + h) * DD];
        float s0 = 0.f, d0 = 0.f, s1 = 0.f, d1 = 0.f;
#pragma unroll
        for (int j = 0; j < 4; j++) {
            float4 av = as[j], dv = ad[j];
            s0 += hv0[j].x * av.x + hv0[j].y * av.y + hv0[j].z * av.z + hv0[j].w * av.w;
            d0 += hv0[j].x * dv.x + hv0[j].y * dv.y + hv0[j].z * dv.z + hv0[j].w * dv.w;
            s1 += hv1[j].x * av.x + hv1[j].y * av.y + hv1[j].z * av.z + hv1[j].w * av.w;
            d1 += hv1[j].x * dv.x + hv1[j].y * dv.y + hv1[j].z * dv.z + hv1[j].w * dv.w;
        }
        size_t base = (size_t)p * NN * HH;
        g_als[base + (size_t)n0 * HH + h] = s0;
        g_ald[base + (size_t)n0 * HH + h] = d0;
        g_als[base + (size_t)n1 * HH + h] = s1;
        g_ald[base + (size_t)n1 * HH + h] = d1;
    }
}

// ---------------- edge pass B (gridDim.y = metapath) ----------------
__global__ void edgeB_kernel(const void* __restrict__ ei)
{
    int e = blockIdx.x * blockDim.x + threadIdx.x;
    if (e >= EE) return;
    int p = blockIdx.y;
    long long s = load_idx(ei, (size_t)(2 * p) * EE + e);
    long long d = load_idx(ei, (size_t)(2 * p + 1) * EE + e);
    const float* als = &g_als[(size_t)p * NN * HH];
    const float* ald = &g_ald[(size_t)p * NN * HH];
    float4 s0 = *(const float4*)&als[s * 8];
    float4 s1 = *(const float4*)&als[s * 8 + 4];
    float4 d0 = *(const float4*)&ald[d * 8];
    float4 d1 = *(const float4*)&ald[d * 8 + 4];
    float ev[8];
    ev[0] = s0.x + d0.x; ev[1] = s0.y + d0.y; ev[2] = s0.z + d0.z; ev[3] = s0.w + d0.w;
    ev[4] = s1.x + d1.x; ev[5] = s1.y + d1.y; ev[6] = s1.z + d1.z; ev[7] = s1.w + d1.w;
#pragma unroll
    for (int h = 0; h < 8; h++) {
        float x = ev[h];
        x = (x > 0.f) ? x : NEG * x;
        ev[h] = expf(x);
    }
    float* gp = &g_p[((size_t)p * EE + e) * 8];
    *(float4*)gp       = make_float4(ev[0], ev[1], ev[2], ev[3]);
    *(float4*)(gp + 4) = make_float4(ev[4], ev[5], ev[6], ev[7]);
    float* den = &g_denom[(size_t)p * NN * HH + d * 8];
    red_add_v4(den,     make_float4(ev[0], ev[1], ev[2], ev[3]));
    red_add_v4(den + 4, make_float4(ev[4], ev[5], ev[6], ev[7]));
}

// ---------------- edge pass C (warp per edge; gridDim.y = metapath) --------
__global__ void edgeC_kernel(const void* __restrict__ ei)
{
    int gid = blockIdx.x * blockDim.x + threadIdx.x;
    int e = gid >> 5;
    if (e >= EE) return;
    int p = blockIdx.y;
    int l = gid & 31;
    long long s = load_idx(ei, (size_t)(2 * p) * EE + e);
    long long d = load_idx(ei, (size_t)(2 * p + 1) * EE + e);
    int head = l >> 2;
    float pv  = g_p[((size_t)p * EE + e) * 8 + head];
    float den = g_denom[(size_t)p * NN * HH + d * 8 + head];
    float alpha = pv / (den + 1e-16f);
    float4 hv = *(const float4*)&g_h[(size_t)s * CC + l * 4];
    float4 m  = make_float4(hv.x * alpha, hv.y * alpha, hv.z * alpha, hv.w * alpha);
    red_add_v4(&g_outs[((size_t)p * NN + d) * CC + l * 4], m);
}

// ---------------- semantic softmax beta ----------------
__global__ void beta_kernel(const float* __restrict__ q) {
    __shared__ float red[128];
    __shared__ float sc[PP];
    int c = threadIdx.x;
    for (int p = 0; p < PP; p++) {
        red[c] = q[c] * g_w[p * CC + c];
        __syncthreads();
        for (int s = 64; s > 0; s >>= 1) {
            if (c < s) red[c] += red[c + s];
            __syncthreads();
        }
        if (c == 0) sc[p] = red[0] / (float)NN;
        __syncthreads();
    }
    if (c == 0) {
        float m = fmaxf(sc[0], fmaxf(sc[1], sc[2]));
        float e0 = expf(sc[0] - m), e1 = expf(sc[1] - m), e2 = expf(sc[2] - m);
        float s = e0 + e1 + e2;
        g_beta[0] = e0 / s; g_beta[1] = e1 / s; g_beta[2] = e2 / s;
    }
}

// ---------------- fused relu + weighted sum + final linear ----------------
__global__ void final_kernel(const float* __restrict__ linW,
                             const float* __restrict__ linb,
                             float* __restrict__ out)
{
    __shared__ float sW[CC * OUTC];
    __shared__ float sb[OUTC];
    __shared__ float sbeta[PP];
    int t = threadIdx.x;
    for (int i = t; i < CC * OUTC; i += blockDim.x) sW[i] = linW[i];
    if (t < OUTC) sb[t] = linb[t];
    if (t < PP)   sbeta[t] = g_beta[t];
    __syncthreads();
    int n = blockIdx.x * blockDim.x + t;
    if (n >= NN) return;
    float b0 = sbeta[0], b1 = sbeta[1], b2 = sbeta[2];
    const float4* o0 = (const float4*)&g_outs[(size_t)n * CC];
    const float4* o1 = (const float4*)&g_outs[((size_t)NN + n) * CC];
    const float4* o2 = (const float4*)&g_outs[((size_t)2 * NN + n) * CC];
    float a0 = sb[0], a1 = sb[1], a2 = sb[2];
#pragma unroll 8
    for (int c4 = 0; c4 < 32; c4++) {
        float4 v0 = o0[c4], v1 = o1[c4], v2 = o2[c4];
        float f[4];
        f[0] = b0 * fmaxf(v0.x, 0.f) + b1 * fmaxf(v1.x, 0.f) + b2 * fmaxf(v2.x, 0.f);
        f[1] = b0 * fmaxf(v0.y, 0.f) + b1 * fmaxf(v1.y, 0.f) + b2 * fmaxf(v2.y, 0.f);
        f[2] = b0 * fmaxf(v0.z, 0.f) + b1 * fmaxf(v1.z, 0.f) + b2 * fmaxf(v2.z, 0.f);
        f[3] = b0 * fmaxf(v0.w, 0.f) + b1 * fmaxf(v1.w, 0.f) + b2 * fmaxf(v2.w, 0.f);
        int cb = c4 * 4;
#pragma unroll
        for (int j = 0; j < 4; j++) {
            a0 += f[j] * sW[(cb + j) * 3 + 0];
            a1 += f[j] * sW[(cb + j) * 3 + 1];
            a2 += f[j] * sW[(cb + j) * 3 + 2];
        }
    }
    out[n * 3 + 0] = a0;
    out[n * 3 + 1] = a1;
    out[n * 3 + 2] = a2;
}

// ---------------- launch ----------------
extern "C" void kernel_launch(void* const* d_in, const int* in_sizes, int n_in,
                              void* d_out, int out_size)
{
    const float* x      = (const float*)d_in[0];
    const void*  ei     = (const void*)d_in[1];
    const float* W_proj = (const float*)d_in[2];
    const float* b_proj = (const float*)d_in[3];
    const float* a_src  = (const float*)d_in[4];
    const float* a_dst  = (const float*)d_in[5];
    const float* k_W    = (const float*)d_in[6];
    const float* k_b    = (const float*)d_in[7];
    const float* q      = (const float*)d_in[8];
    const float* lin_W  = (const float*)d_in[9];
    const float* lin_b  = (const float*)d_in[10];
    float*       out    = (float*)d_out;

    cudaFuncSetAttribute(gemm_bf16<0>, cudaFuncAttributeMaxDynamicSharedMemorySize, SMEMSZ);
    cudaFuncSetAttribute(gemm_bf16<1>, cudaFuncAttributeMaxDynamicSharedMemorySize, SMEMSZ);

    probe_kernel<<<1, 32>>>(ei);
    convW_kernel<<<(WPROJ_ELEMS + KW_ELEMS + 255) / 256, 256>>>(W_proj, k_W);
    zero_kernel<<<2048, 256>>>();

    gemm_bf16<0><<<(NN + 127) / 128, NTHREADS, SMEMSZ>>>(x, b_proj, NN, FIN);

    alsd_all_kernel<<<((NN / 2) * HH + 255) / 256, 256>>>(a_src, a_dst);
    edgeB_kernel<<<dim3((EE + 255) / 256, PP), 256>>>(ei);
    edgeC_kernel<<<dim3((EE * 32 + 255) / 256, PP), 256>>>(ei);

    gemm_bf16<1><<<(PP * NN + 127) / 128, NTHREADS, SMEMSZ>>>(nullptr, k_b, PP * NN, CC);
    beta_kernel<<<1, 128>>>(q);

    final_kernel<<<(NN + 255) / 256, 256>>>(lin_W, lin_b, out);
}

// round 16
// speedup vs baseline: 1.4529x; 1.4529x over previous
#include <cuda_runtime.h>
#include <cuda_bf16.h>
#include <cstdint>

#define NN   100000
#define FIN  1024
#define HH   8
#define DD   16
#define CC   128
#define EE   600000
#define PP   3
#define OUTC 3
#define NEG  0.2f

#define KSA  40
#define NSB  136

#define OFF_RAWA  0
#define OFF_ASH   32768
#define OFF_ASL   (32768 + 20480)
#define OFF_BSH   (32768 + 40960)
#define OFF_BSL   (32768 + 40960 + 17408)
#define SMEMSZ    (32768 + 40960 + 34816)

#define NNODES    (PP * NN)               // 300000
#define SCAN_BLK  2048
#define NBLK      ((NNODES + SCAN_BLK - 1) / SCAN_BLK)   // 147

// ---------------- scratch (static device globals; no allocs) ----------------
__device__ float g_h[(size_t)NN * CC];
__device__ float g_outs[(size_t)PP * NN * CC];
__device__ float g_p[(size_t)PP * EE * HH];
__device__ float g_als[(size_t)PP * NN * HH];
__device__ float g_ald[(size_t)PP * NN * HH];
__device__ float g_denom[(size_t)PP * NN * HH];
__device__ float g_w[PP * CC];
__device__ float g_beta[PP];
__device__ int   g_is64;
// CSR build
__device__ int g_cnt[NNODES];
__device__ int g_rowstart[NNODES];
__device__ int g_bsum[NBLK];
__device__ unsigned long long g_edges[(size_t)PP * EE];
#define WPROJ_ELEMS (FIN * CC)
#define KW_ELEMS    (CC * CC)
__device__ __nv_bfloat16 g_WH[WPROJ_ELEMS + KW_ELEMS];
__device__ __nv_bfloat16 g_WL[WPROJ_ELEMS + KW_ELEMS];

// ---------------- helpers ----------------
__device__ __forceinline__ void red_add_v4(float* addr, float4 v) {
    asm volatile("red.global.add.v4.f32 [%0], {%1,%2,%3,%4};"
                 :: "l"(addr), "f"(v.x), "f"(v.y), "f"(v.z), "f"(v.w)
                 : "memory");
}

__device__ __forceinline__ long long load_idx(const void* ei, size_t pos) {
    if (g_is64) return ((const long long*)ei)[pos];
    return (long long)((const int*)ei)[pos];
}

__device__ __forceinline__ void split2f(float v0, float v1, uint32_t& hi, uint32_t& lo) {
    asm("cvt.rn.bf16x2.f32 %0, %1, %2;" : "=r"(hi) : "f"(v1), "f"(v0));
    float h0 = __uint_as_float(hi << 16);
    float h1 = __uint_as_float(hi & 0xffff0000u);
    float l0 = v0 - h0;
    float l1 = v1 - h1;
    asm("cvt.rn.bf16x2.f32 %0, %1, %2;" : "=r"(lo) : "f"(l1), "f"(l0));
}

__device__ __forceinline__ void mma16816(float* c, const uint32_t* a, const uint32_t* b) {
    asm volatile(
        "mma.sync.aligned.m16n8k16.row.col.f32.bf16.bf16.f32 "
        "{%0,%1,%2,%3}, {%4,%5,%6,%7}, {%8,%9}, {%0,%1,%2,%3};"
        : "+f"(c[0]), "+f"(c[1]), "+f"(c[2]), "+f"(c[3])
        : "r"(a[0]), "r"(a[1]), "r"(a[2]), "r"(a[3]), "r"(b[0]), "r"(b[1]));
}

__device__ __forceinline__ void ldm_x2_t(uint32_t& r0, uint32_t& r1, uint32_t saddr) {
    asm volatile("ldmatrix.sync.aligned.m8n8.x2.trans.shared.b16 {%0,%1}, [%2];"
                 : "=r"(r0), "=r"(r1) : "r"(saddr));
}

__device__ __forceinline__ void cp16(void* sdst, const void* gsrc) {
    uint32_t s = (uint32_t)__cvta_generic_to_shared(sdst);
    asm volatile("cp.async.cg.shared.global [%0], [%1], 16;" :: "r"(s), "l"(gsrc));
}
#define CP_COMMIT() asm volatile("cp.async.commit_group;")

// ---------------- dtype probe ----------------
__global__ void probe_kernel(const void* ei) {
    if (threadIdx.x == 0 && blockIdx.x == 0) {
        const long long* p64 = (const long long*)ei;
        int ok = 1;
#pragma unroll
        for (int i = 0; i < 16; i++) {
            long long v = p64[i];
            if (v < 0 || v >= NN) ok = 0;
        }
        g_is64 = ok;
    }
}

// ---------------- preconvert weights to bf16 hi/lo (k-major) ----------------
__global__ void convW_kernel(const float* __restrict__ Wp,
                             const float* __restrict__ kW)
{
    int i = blockIdx.x * blockDim.x + threadIdx.x;
    if (i >= WPROJ_ELEMS + KW_ELEMS) return;
    float v = (i < WPROJ_ELEMS) ? Wp[i] : kW[i - WPROJ_ELEMS];
    __nv_bfloat16 h = __float2bfloat16_rn(v);
    g_WH[i] = h;
    g_WL[i] = __float2bfloat16_rn(v - __bfloat162float(h));
}

// ---------------- zero accumulators (denom, w, cnt; NOT g_outs) -------------
__global__ void zero_kernel() {
    size_t i = (size_t)blockIdx.x * blockDim.x + threadIdx.x;
    size_t stride = (size_t)gridDim.x * blockDim.x;
    float4 z = make_float4(0.f, 0.f, 0.f, 0.f);
    const size_t n_den4 = (size_t)PP * NN * HH / 4;
    float4* pd = (float4*)g_denom;
    for (size_t j = i; j < n_den4; j += stride) pd[j] = z;
    for (size_t j = i; j < NNODES; j += stride) g_cnt[j] = 0;
    if (i < PP * CC) g_w[i] = 0.f;
}

// ---------------- CSR build: histogram ----------------
__global__ void hist_kernel(const void* __restrict__ ei) {
    int e = blockIdx.x * blockDim.x + threadIdx.x;
    if (e >= EE) return;
    int p = blockIdx.y;
    long long d = load_idx(ei, (size_t)(2 * p + 1) * EE + e);
    atomicAdd(&g_cnt[p * NN + (int)d], 1);
}

// ---------------- CSR build: 3-step exclusive scan ----------------
__global__ void scan1_kernel() {   // 256 threads, SCAN_BLK elems per block
    __shared__ int sh[256];
    int t = threadIdx.x;
    int base = blockIdx.x * SCAN_BLK + t * 8;
    int pre[8];
    int tot = 0;
#pragma unroll
    for (int j = 0; j < 8; j++) {
        int idx = base + j;
        int v = (idx < NNODES) ? g_cnt[idx] : 0;
        pre[j] = tot;
        tot += v;
    }
    sh[t] = tot;
    __syncthreads();
    for (int off = 1; off < 256; off <<= 1) {
        int v = (t >= off) ? sh[t - off] : 0;
        __syncthreads();
        sh[t] += v;
        __syncthreads();
    }
    int thOff = sh[t] - tot;
#pragma unroll
    for (int j = 0; j < 8; j++) {
        int idx = base + j;
        if (idx < NNODES) g_rowstart[idx] = thOff + pre[j];
    }
    if (t == 255) g_bsum[blockIdx.x] = sh[255];
}

__global__ void scan2_kernel() {   // single thread: 147 entries
    if (threadIdx.x == 0) {
        int run = 0;
        for (int i = 0; i < NBLK; i++) { int v = g_bsum[i]; g_bsum[i] = run; run += v; }
    }
}

__global__ void scan3_kernel() {   // add block offsets; reset cnt to 0 (cursor)
    int i = blockIdx.x * blockDim.x + threadIdx.x;
    if (i >= NNODES) return;
    g_rowstart[i] += g_bsum[i / SCAN_BLK];
    g_cnt[i] = 0;
}

// ---------------- CSR build: scatter packed (src, e) ----------------
__global__ void scatter_kernel(const void* __restrict__ ei) {
    int e = blockIdx.x * blockDim.x + threadIdx.x;
    if (e >= EE) return;
    int p = blockIdx.y;
    long long s = load_idx(ei, (size_t)(2 * p) * EE + e);
    long long d = load_idx(ei, (size_t)(2 * p + 1) * EE + e);
    int node = p * NN + (int)d;
    int pos = g_rowstart[node] + atomicAdd(&g_cnt[node], 1);
    g_edges[pos] = (unsigned long long)(unsigned int)s
                 | ((unsigned long long)(unsigned int)e << 32);
}

// ---------------- R14 GEMM (proven best: 2 CTA/SM, single barrier/tile) -----
template <int MODE>
__global__ __launch_bounds__(256, 2) void gemm_bf16(
    const float* __restrict__ Aext, const float* __restrict__ bias, int M, int K)
{
    extern __shared__ __align__(16) char dsm[];
    float*    rawA = (float*)(dsm + OFF_RAWA);
    uint16_t* ASH  = (uint16_t*)(dsm + OFF_ASH);
    uint16_t* ASL  = (uint16_t*)(dsm + OFF_ASL);
    uint16_t* BSH  = (uint16_t*)(dsm + OFF_BSH);
    uint16_t* BSL  = (uint16_t*)(dsm + OFF_BSL);
    __shared__ float colsum[128];

    const float* __restrict__ A = (MODE == 0) ? Aext : g_outs;
    const __nv_bfloat16* __restrict__ BH = (MODE == 0) ? g_WH : (g_WH + WPROJ_ELEMS);
    const __nv_bfloat16* __restrict__ BL = (MODE == 0) ? g_WL : (g_WL + WPROJ_ELEMS);

    int tid  = threadIdx.x;
    int lane = tid & 31;
    int wid  = tid >> 5;
    int wm = wid & 3;
    int wn = wid >> 2;
    int g  = lane >> 2;
    int t  = lane & 3;
    int row0 = blockIdx.x * 128;
    int nT = K / 32;
    int rstart = wm * 32 + wn * 16;

    float acc[2][8][4];
#pragma unroll
    for (int mt = 0; mt < 2; mt++)
#pragma unroll
        for (int nt = 0; nt < 8; nt++)
#pragma unroll
            for (int j = 0; j < 4; j++) acc[mt][nt][j] = 0.f;

#define ISSUE_TILE(tt) do {                                                      \
        int _s = (tt) & 1;                                                       \
        int _k0 = (tt) * 32;                                                     \
        float* _ra = rawA + _s * 4096;                                           \
        _Pragma("unroll")                                                        \
        for (int j = 0; j < 4; j++) {                                            \
            int idx = lane + j * 32;                                             \
            int r_  = rstart + (idx >> 3);                                       \
            int k4_ = (idx & 7) * 4;                                             \
            int gr = row0 + r_; if (gr > M - 1) gr = M - 1;                      \
            cp16(&_ra[r_ * 32 + k4_], &A[(size_t)gr * K + _k0 + k4_]);           \
        }                                                                        \
        uint16_t* _bh = BSH + _s * 32 * NSB;                                     \
        uint16_t* _bl = BSL + _s * 32 * NSB;                                     \
        _Pragma("unroll")                                                        \
        for (int it = 0; it < 2; it++) {                                         \
            int chunk = tid + it * 256;                                          \
            int r_  = chunk >> 4;                                                \
            int c8_ = (chunk & 15) * 8;                                          \
            cp16(&_bh[r_ * NSB + c8_], &BH[(size_t)(_k0 + r_) * 128 + c8_]);     \
            cp16(&_bl[r_ * NSB + c8_], &BL[(size_t)(_k0 + r_) * 128 + c8_]);     \
        }                                                                        \
        asm volatile("cp.async.commit_group;");                                  \
    } while (0)

#define CONVERT_TILE(tt) do {                                                    \
        int _s = (tt) & 1;                                                       \
        float* _ra = rawA + _s * 4096;                                           \
        uint16_t* _ah = ASH + _s * 128 * KSA;                                    \
        uint16_t* _al = ASL + _s * 128 * KSA;                                    \
        _Pragma("unroll")                                                        \
        for (int j = 0; j < 4; j++) {                                            \
            int idx = lane + j * 32;                                             \
            int r_  = rstart + (idx >> 3);                                       \
            int k4_ = (idx & 7) * 4;                                             \
            float4 v = *(const float4*)&_ra[r_ * 32 + k4_];                      \
            if (MODE == 1) {                                                     \
                v.x = fmaxf(v.x, 0.f); v.y = fmaxf(v.y, 0.f);                    \
                v.z = fmaxf(v.z, 0.f); v.w = fmaxf(v.w, 0.f);                    \
            }                                                                    \
            uint32_t h01, l01, h23, l23;                                         \
            split2f(v.x, v.y, h01, l01);                                         \
            split2f(v.z, v.w, h23, l23);                                         \
            *(uint32_t*)&_ah[r_ * KSA + k4_]     = h01;                          \
            *(uint32_t*)&_ah[r_ * KSA + k4_ + 2] = h23;                          \
            *(uint32_t*)&_al[r_ * KSA + k4_]     = l01;                          \
            *(uint32_t*)&_al[r_ * KSA + k4_ + 2] = l23;                          \
        }                                                                        \
    } while (0)

    ISSUE_TILE(0);
    asm volatile("cp.async.wait_group 0;");
    CONVERT_TILE(0);
    __syncthreads();

    for (int i = 0; i < nT; i++) {
        int buf = i & 1;
        if (i + 1 < nT) ISSUE_TILE(i + 1);

        const uint16_t* aH = ASH + buf * 128 * KSA;
        const uint16_t* aL = ASL + buf * 128 * KSA;
        const uint16_t* bH = BSH + buf * 32 * NSB;
        const uint16_t* bL = BSL + buf * 32 * NSB;

#pragma unroll
        for (int ks = 0; ks < 32; ks += 16) {
            uint32_t ah[2][4], al[2][4];
#pragma unroll
            for (int mt = 0; mt < 2; mt++) {
                int r = wm * 32 + mt * 16 + g;
                const uint16_t* pH = &aH[r * KSA + ks + 2 * t];
                const uint16_t* pL = &aL[r * KSA + ks + 2 * t];
                ah[mt][0] = *(const uint32_t*)pH;
                ah[mt][1] = *(const uint32_t*)(pH + 8 * KSA);
                ah[mt][2] = *(const uint32_t*)(pH + 8);
                ah[mt][3] = *(const uint32_t*)(pH + 8 * KSA + 8);
                al[mt][0] = *(const uint32_t*)pL;
                al[mt][1] = *(const uint32_t*)(pL + 8 * KSA);
                al[mt][2] = *(const uint32_t*)(pL + 8);
                al[mt][3] = *(const uint32_t*)(pL + 8 * KSA + 8);
            }
#pragma unroll
            for (int nt = 0; nt < 8; nt++) {
                int nb2 = wn * 64 + nt * 8;
                uint32_t bh[2], bl[2];
                uint32_t srcH = (uint32_t)__cvta_generic_to_shared(
                    &bH[(ks + (lane & 15)) * NSB + nb2]);
                uint32_t srcL = (uint32_t)__cvta_generic_to_shared(
                    &bL[(ks + (lane & 15)) * NSB + nb2]);
                ldm_x2_t(bh[0], bh[1], srcH);
                ldm_x2_t(bl[0], bl[1], srcL);
#pragma unroll
                for (int mt = 0; mt < 2; mt++) {
                    mma16816(acc[mt][nt], ah[mt], bh);
                    mma16816(acc[mt][nt], ah[mt], bl);
                    mma16816(acc[mt][nt], al[mt], bh);
                }
            }
        }

        if (i + 1 < nT) {
            asm volatile("cp.async.wait_group 0;");
            CONVERT_TILE(i + 1);
        }
        __syncthreads();
    }
#undef ISSUE_TILE
#undef CONVERT_TILE

    if (MODE == 0) {
#pragma unroll
        for (int mt = 0; mt < 2; mt++) {
            int r0 = row0 + wm * 32 + mt * 16 + g;
#pragma unroll
            for (int nt = 0; nt < 8; nt++) {
                int c = wn * 64 + nt * 8 + 2 * t;
                float b0 = bias[c], b1 = bias[c + 1];
                if (r0 < M) {
                    float2 s = make_float2(acc[mt][nt][0] + b0, acc[mt][nt][1] + b1);
                    *(float2*)&g_h[(size_t)r0 * 128 + c] = s;
                }
                int r1 = r0 + 8;
                if (r1 < M) {
                    float2 s = make_float2(acc[mt][nt][2] + b0, acc[mt][nt][3] + b1);
                    *(float2*)&g_h[(size_t)r1 * 128 + c] = s;
                }
            }
        }
    } else {
        bool crossing = (row0 / NN) != ((row0 + 127) / NN);
        if (!crossing) {
            int p = row0 / NN;
            float cs[8][2];
#pragma unroll
            for (int nt = 0; nt < 8; nt++) { cs[nt][0] = 0.f; cs[nt][1] = 0.f; }
#pragma unroll
            for (int mt = 0; mt < 2; mt++) {
                int r0 = row0 + wm * 32 + mt * 16 + g;
                int r1 = r0 + 8;
#pragma unroll
                for (int nt = 0; nt < 8; nt++) {
                    int c = wn * 64 + nt * 8 + 2 * t;
                    float b0 = bias[c], b1 = bias[c + 1];
                    if (r0 < M) {
                        cs[nt][0] += tanhf(acc[mt][nt][0] + b0);
                        cs[nt][1] += tanhf(acc[mt][nt][1] + b1);
                    }
                    if (r1 < M) {
                        cs[nt][0] += tanhf(acc[mt][nt][2] + b0);
                        cs[nt][1] += tanhf(acc[mt][nt][3] + b1);
                    }
                }
            }
#pragma unroll
            for (int nt = 0; nt < 8; nt++) {
#pragma unroll
                for (int m = 4; m <= 16; m <<= 1) {
                    cs[nt][0] += __shfl_xor_sync(0xffffffffu, cs[nt][0], m);
                    cs[nt][1] += __shfl_xor_sync(0xffffffffu, cs[nt][1], m);
                }
            }
            if (tid < 128) colsum[tid] = 0.f;
            __syncthreads();
            if (g == 0) {
#pragma unroll
                for (int nt = 0; nt < 8; nt++) {
                    int c = wn * 64 + nt * 8 + 2 * t;
                    atomicAdd(&colsum[c], cs[nt][0]);
                    atomicAdd(&colsum[c + 1], cs[nt][1]);
                }
            }
            __syncthreads();
            if (tid < 128) atomicAdd(&g_w[p * CC + tid], colsum[tid]);
        } else {
#pragma unroll
            for (int mt = 0; mt < 2; mt++) {
                int r0 = row0 + wm * 32 + mt * 16 + g;
                int r1 = r0 + 8;
#pragma unroll
                for (int nt = 0; nt < 8; nt++) {
                    int c = wn * 64 + nt * 8 + 2 * t;
                    float b0 = bias[c], b1 = bias[c + 1];
                    if (r0 < M) {
                        atomicAdd(&g_w[(r0 / NN) * CC + c],     tanhf(acc[mt][nt][0] + b0));
                        atomicAdd(&g_w[(r0 / NN) * CC + c + 1], tanhf(acc[mt][nt][1] + b1));
                    }
                    if (r1 < M) {
                        atomicAdd(&g_w[(r1 / NN) * CC + c],     tanhf(acc[mt][nt][2] + b0));
                        atomicAdd(&g_w[(r1 / NN) * CC + c + 1], tanhf(acc[mt][nt][3] + b1));
                    }
                }
            }
        }
    }
}

// ------- attention logits, all metapaths, 2 nodes per thread -------
__global__ void alsd_all_kernel(const float* __restrict__ asrc,
                                const float* __restrict__ adst)
{
    int i = blockIdx.x * blockDim.x + threadIdx.x;
    if (i >= (NN / 2) * HH) return;
    int h  = i & 7;
    int n0 = (i >> 3) * 2;
    int n1 = n0 + 1;
    float4 hv0[4], hv1[4];
    const float4* hp0 = (const float4*)&g_h[(size_t)n0 * CC + h * DD];
    const float4* hp1 = (const float4*)&g_h[(size_t)n1 * CC + h * DD];
#pragma unroll
    for (int j = 0; j < 4; j++) { hv0[j] = hp0[j]; hv1[j] = hp1[j]; }
#pragma unroll
    for (int p = 0; p < PP; p++) {
        const float4* as = (const float4*)&asrc[(p * HH + h) * DD];
        const float4* ad = (const float4*)&adst[(p * HH + h) * DD];
        float s0 = 0.f, d0 = 0.f, s1 = 0.f, d1 = 0.f;
#pragma unroll
        for (int j = 0; j < 4; j++) {
            float4 av = as[j], dv = ad[j];
            s0 += hv0[j].x * av.x + hv0[j].y * av.y + hv0[j].z * av.z + hv0[j].w * av.w;
            d0 += hv0[j].x * dv.x + hv0[j].y * dv.y + hv0[j].z * dv.z + hv0[j].w * dv.w;
            s1 += hv1[j].x * av.x + hv1[j].y * av.y + hv1[j].z * av.z + hv1[j].w * av.w;
            d1 += hv1[j].x * dv.x + hv1[j].y * dv.y + hv1[j].z * dv.z + hv1[j].w * dv.w;
        }
        size_t base = (size_t)p * NN * HH;
        g_als[base + (size_t)n0 * HH + h] = s0;
        g_ald[base + (size_t)n0 * HH + h] = d0;
        g_als[base + (size_t)n1 * HH + h] = s1;
        g_ald[base + (size_t)n1 * HH + h] = d1;
    }
}

// ---------------- edge pass B (gridDim.y = metapath) ----------------
__global__ void edgeB_kernel(const void* __restrict__ ei)
{
    int e = blockIdx.x * blockDim.x + threadIdx.x;
    if (e >= EE) return;
    int p = blockIdx.y;
    long long s = load_idx(ei, (size_t)(2 * p) * EE + e);
    long long d = load_idx(ei, (size_t)(2 * p + 1) * EE + e);
    const float* als = &g_als[(size_t)p * NN * HH];
    const float* ald = &g_ald[(size_t)p * NN * HH];
    float4 s0 = *(const float4*)&als[s * 8];
    float4 s1 = *(const float4*)&als[s * 8 + 4];
    float4 d0 = *(const float4*)&ald[d * 8];
    float4 d1 = *(const float4*)&ald[d * 8 + 4];
    float ev[8];
    ev[0] = s0.x + d0.x; ev[1] = s0.y + d0.y; ev[2] = s0.z + d0.z; ev[3] = s0.w + d0.w;
    ev[4] = s1.x + d1.x; ev[5] = s1.y + d1.y; ev[6] = s1.z + d1.z; ev[7] = s1.w + d1.w;
#pragma unroll
    for (int h = 0; h < 8; h++) {
        float x = ev[h];
        x = (x > 0.f) ? x : NEG * x;
        ev[h] = expf(x);
    }
    float* gp = &g_p[((size_t)p * EE + e) * 8];
    *(float4*)gp       = make_float4(ev[0], ev[1], ev[2], ev[3]);
    *(float4*)(gp + 4) = make_float4(ev[4], ev[5], ev[6], ev[7]);
    float* den = &g_denom[(size_t)p * NN * HH + d * 8];
    red_add_v4(den,     make_float4(ev[0], ev[1], ev[2], ev[3]));
    red_add_v4(den + 4, make_float4(ev[4], ev[5], ev[6], ev[7]));
}

// -------- node aggregation: one warp per (metapath, dst), no atomics --------
__global__ void nodeC_kernel()
{
    int gw = (blockIdx.x * blockDim.x + threadIdx.x) >> 5;
    if (gw >= NNODES) return;
    int l = threadIdx.x & 31;
    int p = gw / NN;
    int head = l >> 2;
    int rs  = g_rowstart[gw];
    int cnt = g_cnt[gw];
    float den = g_denom[(size_t)gw * 8 + head];
    float inv = 1.f / (den + 1e-16f);
    float4 acc = make_float4(0.f, 0.f, 0.f, 0.f);
    const unsigned long long* ep = &g_edges[rs];
    const float* gp_base = &g_p[(size_t)p * EE * 8];

    if (cnt > 0) {
        unsigned long long pk = ep[0];
        for (int i = 0; i < cnt; i++) {
            unsigned long long nxt = (i + 1 < cnt) ? ep[i + 1] : 0ull;
            int src = (int)(pk & 0xffffffffull);
            int e   = (int)(pk >> 32);
            float pv = gp_base[(size_t)e * 8 + head];
            float a  = pv * inv;
            float4 hv = *(const float4*)&g_h[(size_t)src * CC + l * 4];
            acc.x += hv.x * a; acc.y += hv.y * a;
            acc.z += hv.z * a; acc.w += hv.w * a;
            pk = nxt;
        }
    }
    *(float4*)&g_outs[(size_t)gw * CC + l * 4] = acc;
}

// ---------------- semantic softmax beta ----------------
__global__ void beta_kernel(const float* __restrict__ q) {
    __shared__ float red[128];
    __shared__ float sc[PP];
    int c = threadIdx.x;
    for (int p = 0; p < PP; p++) {
        red[c] = q[c] * g_w[p * CC + c];
        __syncthreads();
        for (int s = 64; s > 0; s >>= 1) {
            if (c < s) red[c] += red[c + s];
            __syncthreads();
        }
        if (c == 0) sc[p] = red[0] / (float)NN;
        __syncthreads();
    }
    if (c == 0) {
        float m = fmaxf(sc[0], fmaxf(sc[1], sc[2]));
        float e0 = expf(sc[0] - m), e1 = expf(sc[1] - m), e2 = expf(sc[2] - m);
        float s = e0 + e1 + e2;
        g_beta[0] = e0 / s; g_beta[1] = e1 / s; g_beta[2] = e2 / s;
    }
}

// ---------------- fused relu + weighted sum + final linear ----------------
__global__ void final_kernel(const float* __restrict__ linW,
                             const float* __restrict__ linb,
                             float* __restrict__ out)
{
    __shared__ float sW[CC * OUTC];
    __shared__ float sb[OUTC];
    __shared__ float sbeta[PP];
    int t = threadIdx.x;
    for (int i = t; i < CC * OUTC; i += blockDim.x) sW[i] = linW[i];
    if (t < OUTC) sb[t] = linb[t];
    if (t < PP)   sbeta[t] = g_beta[t];
    __syncthreads();
    int n = blockIdx.x * blockDim.x + t;
    if (n >= NN) return;
    float b0 = sbeta[0], b1 = sbeta[1], b2 = sbeta[2];
    const float4* o0 = (const float4*)&g_outs[(size_t)n * CC];
    const float4* o1 = (const float4*)&g_outs[((size_t)NN + n) * CC];
    const float4* o2 = (const float4*)&g_outs[((size_t)2 * NN + n) * CC];
    float a0 = sb[0], a1 = sb[1], a2 = sb[2];
#pragma unroll 8
    for (int c4 = 0; c4 < 32; c4++) {
        float4 v0 = o0[c4], v1 = o1[c4], v2 = o2[c4];
        float f[4];
        f[0] = b0 * fmaxf(v0.x, 0.f) + b1 * fmaxf(v1.x, 0.f) + b2 * fmaxf(v2.x, 0.f);
        f[1] = b0 * fmaxf(v0.y, 0.f) + b1 * fmaxf(v1.y, 0.f) + b2 * fmaxf(v2.y, 0.f);
        f[2] = b0 * fmaxf(v0.z, 0.f) + b1 * fmaxf(v1.z, 0.f) + b2 * fmaxf(v2.z, 0.f);
        f[3] = b0 * fmaxf(v0.w, 0.f) + b1 * fmaxf(v1.w, 0.f) + b2 * fmaxf(v2.w, 0.f);
        int cb = c4 * 4;
#pragma unroll
        for (int j = 0; j < 4; j++) {
            a0 += f[j] * sW[(cb + j) * 3 + 0];
            a1 += f[j] * sW[(cb + j) * 3 + 1];
            a2 += f[j] * sW[(cb + j) * 3 + 2];
        }
    }
    out[n * 3 + 0] = a0;
    out[n * 3 + 1] = a1;
    out[n * 3 + 2] = a2;
}

// ---------------- launch ----------------
extern "C" void kernel_launch(void* const* d_in, const int* in_sizes, int n_in,
                              void* d_out, int out_size)
{
    const float* x      = (const float*)d_in[0];
    const void*  ei     = (const void*)d_in[1];
    const float* W_proj = (const float*)d_in[2];
    const float* b_proj = (const float*)d_in[3];
    const float* a_src  = (const float*)d_in[4];
    const float* a_dst  = (const float*)d_in[5];
    const float* k_W    = (const float*)d_in[6];
    const float* k_b    = (const float*)d_in[7];
    const float* q      = (const float*)d_in[8];
    const float* lin_W  = (const float*)d_in[9];
    const float* lin_b  = (const float*)d_in[10];
    float*       out    = (float*)d_out;

    cudaFuncSetAttribute(gemm_bf16<0>, cudaFuncAttributeMaxDynamicSharedMemorySize, SMEMSZ);
    cudaFuncSetAttribute(gemm_bf16<1>, cudaFuncAttributeMaxDynamicSharedMemorySize, SMEMSZ);

    probe_kernel<<<1, 32>>>(ei);
    convW_kernel<<<(WPROJ_ELEMS + KW_ELEMS + 255) / 256, 256>>>(W_proj, k_W);
    zero_kernel<<<2048, 256>>>();

    // CSR build (independent of GEMM; overlaps launch latencies)
    hist_kernel<<<dim3((EE + 255) / 256, PP), 256>>>(ei);
    scan1_kernel<<<NBLK, 256>>>();
    scan2_kernel<<<1, 32>>>();
    scan3_kernel<<<(NNODES + 255) / 256, 256>>>();
    scatter_kernel<<<dim3((EE + 255) / 256, PP), 256>>>(ei);

    gemm_bf16<0><<<(NN + 127) / 128, 256, SMEMSZ>>>(x, b_proj, NN, FIN);

    alsd_all_kernel<<<((NN / 2) * HH + 255) / 256, 256>>>(a_src, a_dst);
    edgeB_kernel<<<dim3((EE + 255) / 256, PP), 256>>>(ei);
    nodeC_kernel<<<(NNODES * 32 + 255) / 256, 256>>>();

    gemm_bf16<1><<<(PP * NN + 127) / 128, 256, SMEMSZ>>>(nullptr, k_b, PP * NN, CC);
    beta_kernel<<<1, 128>>>(q);

    final_kernel<<<(NN + 255) / 256, 256>>>(lin_W, lin_b, out);
}

// round 17
// speedup vs baseline: 1.5086x; 1.0383x over previous
#include <cuda_runtime.h>
#include <cuda_bf16.h>
#include <cstdint>

#define NN   100000
#define FIN  1024
#define HH   8
#define DD   16
#define CC   128
#define EE   600000
#define PP   3
#define OUTC 3
#define NEG  0.2f

#define KSA  40
#define NSB  136

#define OFF_RAWA  0
#define OFF_ASH   32768
#define OFF_ASL   (32768 + 20480)
#define OFF_BSH   (32768 + 40960)
#define OFF_BSL   (32768 + 40960 + 17408)
#define SMEMSZ    (32768 + 40960 + 34816)

#define NNODES    (PP * NN)               // 300000
#define SCAN_BLK  2048
#define NBLK      ((NNODES + SCAN_BLK - 1) / SCAN_BLK)   // 147

// ---------------- scratch (static device globals; no allocs) ----------------
__device__ float g_h[(size_t)NN * CC];
__device__ float g_outs[(size_t)PP * NN * CC];
__device__ float g_p[(size_t)PP * EE * HH];     // CSR-ordered exp(e) values
__device__ float g_als[(size_t)PP * NN * HH];
__device__ float g_ald[(size_t)PP * NN * HH];
__device__ float g_w[PP * CC];
__device__ float g_beta[PP];
__device__ int   g_is64;
// CSR build
__device__ int g_cnt[NNODES];
__device__ int g_rowstart[NNODES];
__device__ int g_bsum[NBLK];
__device__ unsigned int g_esrc[(size_t)PP * EE]; // CSR-ordered src indices
#define WPROJ_ELEMS (FIN * CC)
#define KW_ELEMS    (CC * CC)
__device__ __nv_bfloat16 g_WH[WPROJ_ELEMS + KW_ELEMS];
__device__ __nv_bfloat16 g_WL[WPROJ_ELEMS + KW_ELEMS];

// ---------------- helpers ----------------
__device__ __forceinline__ long long load_idx(const void* ei, size_t pos) {
    if (g_is64) return ((const long long*)ei)[pos];
    return (long long)((const int*)ei)[pos];
}

__device__ __forceinline__ void split2f(float v0, float v1, uint32_t& hi, uint32_t& lo) {
    asm("cvt.rn.bf16x2.f32 %0, %1, %2;" : "=r"(hi) : "f"(v1), "f"(v0));
    float h0 = __uint_as_float(hi << 16);
    float h1 = __uint_as_float(hi & 0xffff0000u);
    float l0 = v0 - h0;
    float l1 = v1 - h1;
    asm("cvt.rn.bf16x2.f32 %0, %1, %2;" : "=r"(lo) : "f"(l1), "f"(l0));
}

__device__ __forceinline__ void mma16816(float* c, const uint32_t* a, const uint32_t* b) {
    asm volatile(
        "mma.sync.aligned.m16n8k16.row.col.f32.bf16.bf16.f32 "
        "{%0,%1,%2,%3}, {%4,%5,%6,%7}, {%8,%9}, {%0,%1,%2,%3};"
        : "+f"(c[0]), "+f"(c[1]), "+f"(c[2]), "+f"(c[3])
        : "r"(a[0]), "r"(a[1]), "r"(a[2]), "r"(a[3]), "r"(b[0]), "r"(b[1]));
}

__device__ __forceinline__ void ldm_x2_t(uint32_t& r0, uint32_t& r1, uint32_t saddr) {
    asm volatile("ldmatrix.sync.aligned.m8n8.x2.trans.shared.b16 {%0,%1}, [%2];"
                 : "=r"(r0), "=r"(r1) : "r"(saddr));
}

__device__ __forceinline__ void cp16(void* sdst, const void* gsrc) {
    uint32_t s = (uint32_t)__cvta_generic_to_shared(sdst);
    asm volatile("cp.async.cg.shared.global [%0], [%1], 16;" :: "r"(s), "l"(gsrc));
}

// ---------------- dtype probe ----------------
__global__ void probe_kernel(const void* ei) {
    if (threadIdx.x == 0 && blockIdx.x == 0) {
        const long long* p64 = (const long long*)ei;
        int ok = 1;
#pragma unroll
        for (int i = 0; i < 16; i++) {
            long long v = p64[i];
            if (v < 0 || v >= NN) ok = 0;
        }
        g_is64 = ok;
    }
}

// ---------------- preconvert weights to bf16 hi/lo (k-major) ----------------
__global__ void convW_kernel(const float* __restrict__ Wp,
                             const float* __restrict__ kW)
{
    int i = blockIdx.x * blockDim.x + threadIdx.x;
    if (i >= WPROJ_ELEMS + KW_ELEMS) return;
    float v = (i < WPROJ_ELEMS) ? Wp[i] : kW[i - WPROJ_ELEMS];
    __nv_bfloat16 h = __float2bfloat16_rn(v);
    g_WH[i] = h;
    g_WL[i] = __float2bfloat16_rn(v - __bfloat162float(h));
}

// ---------------- zero accumulators (cnt + w only) ----------------
__global__ void zero_kernel() {
    size_t i = (size_t)blockIdx.x * blockDim.x + threadIdx.x;
    size_t stride = (size_t)gridDim.x * blockDim.x;
    for (size_t j = i; j < NNODES; j += stride) g_cnt[j] = 0;
    if (i < PP * CC) g_w[i] = 0.f;
}

// ---------------- CSR build: histogram ----------------
__global__ void hist_kernel(const void* __restrict__ ei) {
    int e = blockIdx.x * blockDim.x + threadIdx.x;
    if (e >= EE) return;
    int p = blockIdx.y;
    long long d = load_idx(ei, (size_t)(2 * p + 1) * EE + e);
    atomicAdd(&g_cnt[p * NN + (int)d], 1);
}

// ---------------- CSR build: 3-step exclusive scan ----------------
__global__ void scan1_kernel() {
    __shared__ int sh[256];
    int t = threadIdx.x;
    int base = blockIdx.x * SCAN_BLK + t * 8;
    int pre[8];
    int tot = 0;
#pragma unroll
    for (int j = 0; j < 8; j++) {
        int idx = base + j;
        int v = (idx < NNODES) ? g_cnt[idx] : 0;
        pre[j] = tot;
        tot += v;
    }
    sh[t] = tot;
    __syncthreads();
    for (int off = 1; off < 256; off <<= 1) {
        int v = (t >= off) ? sh[t - off] : 0;
        __syncthreads();
        sh[t] += v;
        __syncthreads();
    }
    int thOff = sh[t] - tot;
#pragma unroll
    for (int j = 0; j < 8; j++) {
        int idx = base + j;
        if (idx < NNODES) g_rowstart[idx] = thOff + pre[j];
    }
    if (t == 255) g_bsum[blockIdx.x] = sh[255];
}

__global__ void scan2_kernel() {
    if (threadIdx.x == 0) {
        int run = 0;
        for (int i = 0; i < NBLK; i++) { int v = g_bsum[i]; g_bsum[i] = run; run += v; }
    }
}

__global__ void scan3_kernel() {
    int i = blockIdx.x * blockDim.x + threadIdx.x;
    if (i >= NNODES) return;
    g_rowstart[i] += g_bsum[i / SCAN_BLK];
    g_cnt[i] = 0;
}

// ------- fused CSR scatter + attention logits + exp (replaces edgeB) -------
// Writes p values directly at CSR positions -> nodeC reads sequentially.
__global__ void scatterB_kernel(const void* __restrict__ ei) {
    int e = blockIdx.x * blockDim.x + threadIdx.x;
    if (e >= EE) return;
    int p = blockIdx.y;
    long long s = load_idx(ei, (size_t)(2 * p) * EE + e);
    long long d = load_idx(ei, (size_t)(2 * p + 1) * EE + e);
    int node = p * NN + (int)d;
    int pos = g_rowstart[node] + atomicAdd(&g_cnt[node], 1);

    const float* als = &g_als[(size_t)p * NN * HH];
    const float* ald = &g_ald[(size_t)p * NN * HH];
    float4 s0 = *(const float4*)&als[s * 8];
    float4 s1 = *(const float4*)&als[s * 8 + 4];
    float4 d0 = *(const float4*)&ald[d * 8];
    float4 d1 = *(const float4*)&ald[d * 8 + 4];
    float ev[8];
    ev[0] = s0.x + d0.x; ev[1] = s0.y + d0.y; ev[2] = s0.z + d0.z; ev[3] = s0.w + d0.w;
    ev[4] = s1.x + d1.x; ev[5] = s1.y + d1.y; ev[6] = s1.z + d1.z; ev[7] = s1.w + d1.w;
#pragma unroll
    for (int h = 0; h < 8; h++) {
        float x = ev[h];
        x = (x > 0.f) ? x : NEG * x;
        ev[h] = expf(x);
    }
    float* gp = &g_p[(size_t)pos * 8];
    *(float4*)gp       = make_float4(ev[0], ev[1], ev[2], ev[3]);
    *(float4*)(gp + 4) = make_float4(ev[4], ev[5], ev[6], ev[7]);
    g_esrc[pos] = (unsigned int)s;
}

// ---------------- R14 GEMM (proven best) ----------------
template <int MODE>
__global__ __launch_bounds__(256, 2) void gemm_bf16(
    const float* __restrict__ Aext, const float* __restrict__ bias, int M, int K)
{
    extern __shared__ __align__(16) char dsm[];
    float*    rawA = (float*)(dsm + OFF_RAWA);
    uint16_t* ASH  = (uint16_t*)(dsm + OFF_ASH);
    uint16_t* ASL  = (uint16_t*)(dsm + OFF_ASL);
    uint16_t* BSH  = (uint16_t*)(dsm + OFF_BSH);
    uint16_t* BSL  = (uint16_t*)(dsm + OFF_BSL);
    __shared__ float colsum[128];

    const float* __restrict__ A = (MODE == 0) ? Aext : g_outs;
    const __nv_bfloat16* __restrict__ BH = (MODE == 0) ? g_WH : (g_WH + WPROJ_ELEMS);
    const __nv_bfloat16* __restrict__ BL = (MODE == 0) ? g_WL : (g_WL + WPROJ_ELEMS);

    int tid  = threadIdx.x;
    int lane = tid & 31;
    int wid  = tid >> 5;
    int wm = wid & 3;
    int wn = wid >> 2;
    int g  = lane >> 2;
    int t  = lane & 3;
    int row0 = blockIdx.x * 128;
    int nT = K / 32;
    int rstart = wm * 32 + wn * 16;

    float acc[2][8][4];
#pragma unroll
    for (int mt = 0; mt < 2; mt++)
#pragma unroll
        for (int nt = 0; nt < 8; nt++)
#pragma unroll
            for (int j = 0; j < 4; j++) acc[mt][nt][j] = 0.f;

#define ISSUE_TILE(tt) do {                                                      \
        int _s = (tt) & 1;                                                       \
        int _k0 = (tt) * 32;                                                     \
        float* _ra = rawA + _s * 4096;                                           \
        _Pragma("unroll")                                                        \
        for (int j = 0; j < 4; j++) {                                            \
            int idx = lane + j * 32;                                             \
            int r_  = rstart + (idx >> 3);                                       \
            int k4_ = (idx & 7) * 4;                                             \
            int gr = row0 + r_; if (gr > M - 1) gr = M - 1;                      \
            cp16(&_ra[r_ * 32 + k4_], &A[(size_t)gr * K + _k0 + k4_]);           \
        }                                                                        \
        uint16_t* _bh = BSH + _s * 32 * NSB;                                     \
        uint16_t* _bl = BSL + _s * 32 * NSB;                                     \
        _Pragma("unroll")                                                        \
        for (int it = 0; it < 2; it++) {                                         \
            int chunk = tid + it * 256;                                          \
            int r_  = chunk >> 4;                                                \
            int c8_ = (chunk & 15) * 8;                                          \
            cp16(&_bh[r_ * NSB + c8_], &BH[(size_t)(_k0 + r_) * 128 + c8_]);     \
            cp16(&_bl[r_ * NSB + c8_], &BL[(size_t)(_k0 + r_) * 128 + c8_]);     \
        }                                                                        \
        asm volatile("cp.async.commit_group;");                                  \
    } while (0)

#define CONVERT_TILE(tt) do {                                                    \
        int _s = (tt) & 1;                                                       \
        float* _ra = rawA + _s * 4096;                                           \
        uint16_t* _ah = ASH + _s * 128 * KSA;                                    \
        uint16_t* _al = ASL + _s * 128 * KSA;                                    \
        _Pragma("unroll")                                                        \
        for (int j = 0; j < 4; j++) {                                            \
            int idx = lane + j * 32;                                             \
            int r_  = rstart + (idx >> 3);                                       \
            int k4_ = (idx & 7) * 4;                                             \
            float4 v = *(const float4*)&_ra[r_ * 32 + k4_];                      \
            if (MODE == 1) {                                                     \
                v.x = fmaxf(v.x, 0.f); v.y = fmaxf(v.y, 0.f);                    \
                v.z = fmaxf(v.z, 0.f); v.w = fmaxf(v.w, 0.f);                    \
            }                                                                    \
            uint32_t h01, l01, h23, l23;                                         \
            split2f(v.x, v.y, h01, l01);                                         \
            split2f(v.z, v.w, h23, l23);                                         \
            *(uint32_t*)&_ah[r_ * KSA + k4_]     = h01;                          \
            *(uint32_t*)&_ah[r_ * KSA + k4_ + 2] = h23;                          \
            *(uint32_t*)&_al[r_ * KSA + k4_]     = l01;                          \
            *(uint32_t*)&_al[r_ * KSA + k4_ + 2] = l23;                          \
        }                                                                        \
    } while (0)

    ISSUE_TILE(0);
    asm volatile("cp.async.wait_group 0;");
    CONVERT_TILE(0);
    __syncthreads();

    for (int i = 0; i < nT; i++) {
        int buf = i & 1;
        if (i + 1 < nT) ISSUE_TILE(i + 1);

        const uint16_t* aH = ASH + buf * 128 * KSA;
        const uint16_t* aL = ASL + buf * 128 * KSA;
        const uint16_t* bH = BSH + buf * 32 * NSB;
        const uint16_t* bL = BSL + buf * 32 * NSB;

#pragma unroll
        for (int ks = 0; ks < 32; ks += 16) {
            uint32_t ah[2][4], al[2][4];
#pragma unroll
            for (int mt = 0; mt < 2; mt++) {
                int r = wm * 32 + mt * 16 + g;
                const uint16_t* pH = &aH[r * KSA + ks + 2 * t];
                const uint16_t* pL = &aL[r * KSA + ks + 2 * t];
                ah[mt][0] = *(const uint32_t*)pH;
                ah[mt][1] = *(const uint32_t*)(pH + 8 * KSA);
                ah[mt][2] = *(const uint32_t*)(pH + 8);
                ah[mt][3] = *(const uint32_t*)(pH + 8 * KSA + 8);
                al[mt][0] = *(const uint32_t*)pL;
                al[mt][1] = *(const uint32_t*)(pL + 8 * KSA);
                al[mt][2] = *(const uint32_t*)(pL + 8);
                al[mt][3] = *(const uint32_t*)(pL + 8 * KSA + 8);
            }
#pragma unroll
            for (int nt = 0; nt < 8; nt++) {
                int nb2 = wn * 64 + nt * 8;
                uint32_t bh[2], bl[2];
                uint32_t srcH = (uint32_t)__cvta_generic_to_shared(
                    &bH[(ks + (lane & 15)) * NSB + nb2]);
                uint32_t srcL = (uint32_t)__cvta_generic_to_shared(
                    &bL[(ks + (lane & 15)) * NSB + nb2]);
                ldm_x2_t(bh[0], bh[1], srcH);
                ldm_x2_t(bl[0], bl[1], srcL);
#pragma unroll
                for (int mt = 0; mt < 2; mt++) {
                    mma16816(acc[mt][nt], ah[mt], bh);
                    mma16816(acc[mt][nt], ah[mt], bl);
                    mma16816(acc[mt][nt], al[mt], bh);
                }
            }
        }

        if (i + 1 < nT) {
            asm volatile("cp.async.wait_group 0;");
            CONVERT_TILE(i + 1);
        }
        __syncthreads();
    }
#undef ISSUE_TILE
#undef CONVERT_TILE

    if (MODE == 0) {
#pragma unroll
        for (int mt = 0; mt < 2; mt++) {
            int r0 = row0 + wm * 32 + mt * 16 + g;
#pragma unroll
            for (int nt = 0; nt < 8; nt++) {
                int c = wn * 64 + nt * 8 + 2 * t;
                float b0 = bias[c], b1 = bias[c + 1];
                if (r0 < M) {
                    float2 s = make_float2(acc[mt][nt][0] + b0, acc[mt][nt][1] + b1);
                    *(float2*)&g_h[(size_t)r0 * 128 + c] = s;
                }
                int r1 = r0 + 8;
                if (r1 < M) {
                    float2 s = make_float2(acc[mt][nt][2] + b0, acc[mt][nt][3] + b1);
                    *(float2*)&g_h[(size_t)r1 * 128 + c] = s;
                }
            }
        }
    } else {
        bool crossing = (row0 / NN) != ((row0 + 127) / NN);
        if (!crossing) {
            int p = row0 / NN;
            float cs[8][2];
#pragma unroll
            for (int nt = 0; nt < 8; nt++) { cs[nt][0] = 0.f; cs[nt][1] = 0.f; }
#pragma unroll
            for (int mt = 0; mt < 2; mt++) {
                int r0 = row0 + wm * 32 + mt * 16 + g;
                int r1 = r0 + 8;
#pragma unroll
                for (int nt = 0; nt < 8; nt++) {
                    int c = wn * 64 + nt * 8 + 2 * t;
                    float b0 = bias[c], b1 = bias[c + 1];
                    if (r0 < M) {
                        cs[nt][0] += tanhf(acc[mt][nt][0] + b0);
                        cs[nt][1] += tanhf(acc[mt][nt][1] + b1);
                    }
                    if (r1 < M) {
                        cs[nt][0] += tanhf(acc[mt][nt][2] + b0);
                        cs[nt][1] += tanhf(acc[mt][nt][3] + b1);
                    }
                }
            }
#pragma unroll
            for (int nt = 0; nt < 8; nt++) {
#pragma unroll
                for (int m = 4; m <= 16; m <<= 1) {
                    cs[nt][0] += __shfl_xor_sync(0xffffffffu, cs[nt][0], m);
                    cs[nt][1] += __shfl_xor_sync(0xffffffffu, cs[nt][1], m);
                }
            }
            if (tid < 128) colsum[tid] = 0.f;
            __syncthreads();
            if (g == 0) {
#pragma unroll
                for (int nt = 0; nt < 8; nt++) {
                    int c = wn * 64 + nt * 8 + 2 * t;
                    atomicAdd(&colsum[c], cs[nt][0]);
                    atomicAdd(&colsum[c + 1], cs[nt][1]);
                }
            }
            __syncthreads();
            if (tid < 128) atomicAdd(&g_w[p * CC + tid], colsum[tid]);
        } else {
#pragma unroll
            for (int mt = 0; mt < 2; mt++) {
                int r0 = row0 + wm * 32 + mt * 16 + g;
                int r1 = r0 + 8;
#pragma unroll
                for (int nt = 0; nt < 8; nt++) {
                    int c = wn * 64 + nt * 8 + 2 * t;
                    float b0 = bias[c], b1 = bias[c + 1];
                    if (r0 < M) {
                        atomicAdd(&g_w[(r0 / NN) * CC + c],     tanhf(acc[mt][nt][0] + b0));
                        atomicAdd(&g_w[(r0 / NN) * CC + c + 1], tanhf(acc[mt][nt][1] + b1));
                    }
                    if (r1 < M) {
                        atomicAdd(&g_w[(r1 / NN) * CC + c],     tanhf(acc[mt][nt][2] + b0));
                        atomicAdd(&g_w[(r1 / NN) * CC + c + 1], tanhf(acc[mt][nt][3] + b1));
                    }
                }
            }
        }
    }
}

// ------- attention logits, all metapaths, 2 nodes per thread -------
__global__ void alsd_all_kernel(const float* __restrict__ asrc,
                                const float* __restrict__ adst)
{
    int i = blockIdx.x * blockDim.x + threadIdx.x;
    if (i >= (NN / 2) * HH) return;
    int h  = i & 7;
    int n0 = (i >> 3) * 2;
    int n1 = n0 + 1;
    float4 hv0[4], hv1[4];
    const float4* hp0 = (const float4*)&g_h[(size_t)n0 * CC + h * DD];
    const float4* hp1 = (const float4*)&g_h[(size_t)n1 * CC + h * DD];
#pragma unroll
    for (int j = 0; j < 4; j++) { hv0[j] = hp0[j]; hv1[j] = hp1[j]; }
#pragma unroll
    for (int p = 0; p < PP; p++) {
        const float4* as = (const float4*)&asrc[(p * HH + h) * DD];
        const float4* ad = (const float4*)&adst[(p * HH + h) * DD];
        float s0 = 0.f, d0 = 0.f, s1 = 0.f, d1 = 0.f;
#pragma unroll
        for (int j = 0; j < 4; j++) {
            float4 av = as[j], dv = ad[j];
            s0 += hv0[j].x * av.x + hv0[j].y * av.y + hv0[j].z * av.z + hv0[j].w * av.w;
            d0 += hv0[j].x * dv.x + hv0[j].y * dv.y + hv0[j].z * dv.z + hv0[j].w * dv.w;
            s1 += hv1[j].x * av.x + hv1[j].y * av.y + hv1[j].z * av.z + hv1[j].w * av.w;
            d1 += hv1[j].x * dv.x + hv1[j].y * dv.y + hv1[j].z * dv.z + hv1[j].w * dv.w;
        }
        size_t base = (size_t)p * NN * HH;
        g_als[base + (size_t)n0 * HH + h] = s0;
        g_ald[base + (size_t)n0 * HH + h] = d0;
        g_als[base + (size_t)n1 * HH + h] = s1;
        g_ald[base + (size_t)n1 * HH + h] = d1;
    }
}

// -------- node aggregation: one warp per (metapath, dst) --------
// den accumulated in-register; p and src read sequentially (CSR order).
__global__ void nodeC_kernel()
{
    int gw = (blockIdx.x * blockDim.x + threadIdx.x) >> 5;
    if (gw >= NNODES) return;
    int l = threadIdx.x & 31;
    int head = l >> 2;
    int rs  = g_rowstart[gw];
    int cnt = g_cnt[gw];
    float den = 0.f;
    float4 acc = make_float4(0.f, 0.f, 0.f, 0.f);
    const unsigned int* sp = &g_esrc[rs];
    const float* pp = &g_p[(size_t)rs * 8];

    for (int i = 0; i < cnt; i++) {
        unsigned int src = sp[i];
        float pv = pp[(size_t)i * 8 + head];
        den += pv;
        float4 hv = *(const float4*)&g_h[(size_t)src * CC + l * 4];
        acc.x += hv.x * pv; acc.y += hv.y * pv;
        acc.z += hv.z * pv; acc.w += hv.w * pv;
    }
    float inv = 1.f / (den + 1e-16f);
    acc.x *= inv; acc.y *= inv; acc.z *= inv; acc.w *= inv;
    *(float4*)&g_outs[(size_t)gw * CC + l * 4] = acc;
}

// ---------------- semantic softmax beta ----------------
__global__ void beta_kernel(const float* __restrict__ q) {
    __shared__ float red[128];
    __shared__ float sc[PP];
    int c = threadIdx.x;
    for (int p = 0; p < PP; p++) {
        red[c] = q[c] * g_w[p * CC + c];
        __syncthreads();
        for (int s = 64; s > 0; s >>= 1) {
            if (c < s) red[c] += red[c + s];
            __syncthreads();
        }
        if (c == 0) sc[p] = red[0] / (float)NN;
        __syncthreads();
    }
    if (c == 0) {
        float m = fmaxf(sc[0], fmaxf(sc[1], sc[2]));
        float e0 = expf(sc[0] - m), e1 = expf(sc[1] - m), e2 = expf(sc[2] - m);
        float s = e0 + e1 + e2;
        g_beta[0] = e0 / s; g_beta[1] = e1 / s; g_beta[2] = e2 / s;
    }
}

// ---------------- fused relu + weighted sum + final linear ----------------
__global__ void final_kernel(const float* __restrict__ linW,
                             const float* __restrict__ linb,
                             float* __restrict__ out)
{
    __shared__ float sW[CC * OUTC];
    __shared__ float sb[OUTC];
    __shared__ float sbeta[PP];
    int t = threadIdx.x;
    for (int i = t; i < CC * OUTC; i += blockDim.x) sW[i] = linW[i];
    if (t < OUTC) sb[t] = linb[t];
    if (t < PP)   sbeta[t] = g_beta[t];
    __syncthreads();
    int n = blockIdx.x * blockDim.x + t;
    if (n >= NN) return;
    float b0 = sbeta[0], b1 = sbeta[1], b2 = sbeta[2];
    const float4* o0 = (const float4*)&g_outs[(size_t)n * CC];
    const float4* o1 = (const float4*)&g_outs[((size_t)NN + n) * CC];
    const float4* o2 = (const float4*)&g_outs[((size_t)2 * NN + n) * CC];
    float a0 = sb[0], a1 = sb[1], a2 = sb[2];
#pragma unroll 8
    for (int c4 = 0; c4 < 32; c4++) {
        float4 v0 = o0[c4], v1 = o1[c4], v2 = o2[c4];
        float f[4];
        f[0] = b0 * fmaxf(v0.x, 0.f) + b1 * fmaxf(v1.x, 0.f) + b2 * fmaxf(v2.x, 0.f);
        f[1] = b0 * fmaxf(v0.y, 0.f) + b1 * fmaxf(v1.y, 0.f) + b2 * fmaxf(v2.y, 0.f);
        f[2] = b0 * fmaxf(v0.z, 0.f) + b1 * fmaxf(v1.z, 0.f) + b2 * fmaxf(v2.z, 0.f);
        f[3] = b0 * fmaxf(v0.w, 0.f) + b1 * fmaxf(v1.w, 0.f) + b2 * fmaxf(v2.w, 0.f);
        int cb = c4 * 4;
#pragma unroll
        for (int j = 0; j < 4; j++) {
            a0 += f[j] * sW[(cb + j) * 3 + 0];
            a1 += f[j] * sW[(cb + j) * 3 + 1];
            a2 += f[j] * sW[(cb + j) * 3 + 2];
        }
    }
    out[n * 3 + 0] = a0;
    out[n * 3 + 1] = a1;
    out[n * 3 + 2] = a2;
}

// ---------------- launch ----------------
extern "C" void kernel_launch(void* const* d_in, const int* in_sizes, int n_in,
                              void* d_out, int out_size)
{
    const float* x      = (const float*)d_in[0];
    const void*  ei     = (const void*)d_in[1];
    const float* W_proj = (const float*)d_in[2];
    const float* b_proj = (const float*)d_in[3];
    const float* a_src  = (const float*)d_in[4];
    const float* a_dst  = (const float*)d_in[5];
    const float* k_W    = (const float*)d_in[6];
    const float* k_b    = (const float*)d_in[7];
    const float* q      = (const float*)d_in[8];
    const float* lin_W  = (const float*)d_in[9];
    const float* lin_b  = (const float*)d_in[10];
    float*       out    = (float*)d_out;

    cudaFuncSetAttribute(gemm_bf16<0>, cudaFuncAttributeMaxDynamicSharedMemorySize, SMEMSZ);
    cudaFuncSetAttribute(gemm_bf16<1>, cudaFuncAttributeMaxDynamicSharedMemorySize, SMEMSZ);

    probe_kernel<<<1, 32>>>(ei);
    convW_kernel<<<(WPROJ_ELEMS + KW_ELEMS + 255) / 256, 256>>>(W_proj, k_W);
    zero_kernel<<<2048, 256>>>();

    // CSR skeleton
    hist_kernel<<<dim3((EE + 255) / 256, PP), 256>>>(ei);
    scan1_kernel<<<NBLK, 256>>>();
    scan2_kernel<<<1, 32>>>();
    scan3_kernel<<<(NNODES + 255) / 256, 256>>>();

    gemm_bf16<0><<<(NN + 127) / 128, 256, SMEMSZ>>>(x, b_proj, NN, FIN);
    alsd_all_kernel<<<((NN / 2) * HH + 255) / 256, 256>>>(a_src, a_dst);

    // fused scatter + logits + exp (CSR-ordered p)
    scatterB_kernel<<<dim3((EE + 255) / 256, PP), 256>>>(ei);
    nodeC_kernel<<<(NNODES * 32 + 255) / 256, 256>>>();

    gemm_bf16<1><<<(PP * NN + 127) / 128, 256, SMEMSZ>>>(nullptr, k_b, PP * NN, CC);
    beta_kernel<<<1, 128>>>(q);

    final_kernel<<<(NN + 255) / 256, 256>>>(lin_W, lin_b, out);
}